// round 3
// baseline (speedup 1.0000x reference)
#include <cuda_runtime.h>
#include <cuda_fp16.h>
#include <cstdint>

#define N_NODES 10000
#define N_EDGES 640000
#define FDIM    128
#define NGRAPH  64
#define MAXD    192

// ---------------- device scratch (no allocation allowed) ----------------
__device__ int    g_deg[N_NODES];
__device__ float  g_dis[N_NODES];
__device__ int    g_bucket[N_NODES * MAXD];      // per-dst neighbor lists
__device__ __half g_xh[N_NODES * FDIM];          // fp16 copy of input X
__device__ __half g_wh0[FDIM * FDIM];            // fp16 weights
__device__ __half g_wh1[FDIM * FDIM];
__device__ __half g_wh2[FDIM * FDIM];
__device__ __half g_gbuf[N_NODES * FDIM];        // GEMM output, dis-prescaled, fp16
__device__ __half g_h16[N_NODES * FDIM];         // agg output fp16 (layers 0,1)
__device__ float  g_hbuf[N_NODES * FDIM];        // agg output fp32 (layer 2)
__device__ int    g_starts[NGRAPH + 1];

// ---------------- one-pass bucket CSR ----------------
__global__ void k_zero_deg() {
    int n = blockIdx.x * blockDim.x + threadIdx.x;
    if (n < N_NODES) g_deg[n] = 0;
}

// 4 edges per thread for atomic MLP
__global__ void k_bucket4(const int* __restrict__ src, const int* __restrict__ dst) {
    int i = blockIdx.x * blockDim.x + threadIdx.x;
    if (i >= N_EDGES / 4) return;
    int4 s = ((const int4*)src)[i];
    int4 d = ((const int4*)dst)[i];
    int p;
    p = atomicAdd(&g_deg[d.x], 1); if (p < MAXD) g_bucket[d.x * MAXD + p] = s.x;
    p = atomicAdd(&g_deg[d.y], 1); if (p < MAXD) g_bucket[d.y * MAXD + p] = s.y;
    p = atomicAdd(&g_deg[d.z], 1); if (p < MAXD) g_bucket[d.z * MAXD + p] = s.z;
    p = atomicAdd(&g_deg[d.w], 1); if (p < MAXD) g_bucket[d.w * MAXD + p] = s.w;
}

// dis = rsqrt(deg+1); also graph-boundary starts (batch is sorted)
__global__ void k_dis_starts(const int* __restrict__ batch) {
    int n = blockIdx.x * blockDim.x + threadIdx.x;
    if (n >= N_NODES) return;
    g_dis[n] = rsqrtf((float)g_deg[n] + 1.0f);
    int b1 = batch[n];
    if (n == 0) {
        for (int b = 0; b <= b1; b++) g_starts[b] = 0;
    } else {
        int b0 = batch[n - 1];
        for (int b = b0 + 1; b <= b1; b++) g_starts[b] = n;
    }
    if (n == N_NODES - 1) {
        for (int b = b1 + 1; b <= NGRAPH; b++) g_starts[b] = N_NODES;
    }
}

// ---------------- fp32 -> fp16 conversion (n4 = count of float4) ----------------
__global__ void k_f2h(const float* __restrict__ in, __half* __restrict__ out, int n4) {
    int i = blockIdx.x * blockDim.x + threadIdx.x;
    if (i >= n4) return;
    float4 v = ((const float4*)in)[i];
    __half2 h0 = __floats2half2_rn(v.x, v.y);
    __half2 h1 = __floats2half2_rn(v.z, v.w);
    uint2 o;
    *(__half2*)&o.x = h0;
    *(__half2*)&o.y = h1;
    ((uint2*)out)[i] = o;
}

// ---------------- HMMA GEMM: OUT[n][:] = half( dis[n] * (A[n][:] @ W) ) ----------------
// A fp16 [M,128] row-major, W fp16 [128,128] row-major. block=128 thr (4 warps),
// 64 rows/block, warp = 16 rows x 128 cols. Whole W + A tile in smem, ldmatrix feed.
__device__ __forceinline__ int swz(int row, int col8) {   // half-index; col8 = col/8
    return row * FDIM + ((col8 ^ (row & 7)) << 3);
}

__global__ __launch_bounds__(128) void k_gemm(const __half* __restrict__ A,
                                              const __half* __restrict__ Wh,
                                              __half* __restrict__ OUT) {
    __shared__ __half Wsh[FDIM * FDIM];   // 32 KB
    __shared__ __half Ash[64 * FDIM];     // 16 KB
    int tid  = threadIdx.x;
    int lane = tid & 31;
    int warp = tid >> 5;
    int row0 = blockIdx.x * 64;

    // load W: 2048 uint4, 16 per thread
    #pragma unroll
    for (int i = 0; i < 16; i++) {
        int idx  = tid + i * 128;
        int r    = idx >> 4;
        int c8   = idx & 15;
        *(uint4*)&Wsh[swz(r, c8)] = ((const uint4*)Wh)[idx];
    }
    // load A tile: 1024 uint4, 8 per thread (zero-fill OOB rows)
    #pragma unroll
    for (int i = 0; i < 8; i++) {
        int idx = tid + i * 128;
        int r   = idx >> 4;
        int c8  = idx & 15;
        int gr  = row0 + r;
        uint4 v = make_uint4(0, 0, 0, 0);
        if (gr < N_NODES) v = ((const uint4*)A)[gr * 16 + c8];
        *(uint4*)&Ash[swz(r, c8)] = v;
    }
    __syncthreads();

    float acc[16][4];
    #pragma unroll
    for (int nt = 0; nt < 16; nt++)
        #pragma unroll
        for (int c = 0; c < 4; c++) acc[nt][c] = 0.f;

    int m  = lane >> 3;      // ldmatrix sub-matrix id 0..3
    int l7 = lane & 7;

    #pragma unroll
    for (int kk = 0; kk < 8; kk++) {
        int k0 = kk * 16;
        // A fragment: rows warp*16 + (m&1)*8 + l7, col k0 + (m>>1)*8
        uint32_t a0, a1, a2, a3;
        {
            int rl = warp * 16 + ((m & 1) << 3) + l7;
            int c8 = (k0 >> 3) + (m >> 1);
            uint32_t addr = (uint32_t)__cvta_generic_to_shared(&Ash[swz(rl, c8)]);
            asm volatile("ldmatrix.sync.aligned.m8n8.x4.shared.b16 {%0,%1,%2,%3}, [%4];"
                         : "=r"(a0), "=r"(a1), "=r"(a2), "=r"(a3) : "r"(addr));
        }
        #pragma unroll
        for (int nb = 0; nb < 8; nb++) {          // 16-wide n chunks
            int n0 = nb * 16;
            // B fragment (trans): rows k0 + (m&1)*8 + l7, col n0 + (m>>1)*8
            uint32_t b0, b1, b2, b3;
            {
                int rl = k0 + ((m & 1) << 3) + l7;
                int c8 = (n0 >> 3) + (m >> 1);
                uint32_t addr = (uint32_t)__cvta_generic_to_shared(&Wsh[swz(rl, c8)]);
                asm volatile("ldmatrix.sync.aligned.m8n8.x4.trans.shared.b16 {%0,%1,%2,%3}, [%4];"
                             : "=r"(b0), "=r"(b1), "=r"(b2), "=r"(b3) : "r"(addr));
            }
            float* c0 = acc[nb * 2];
            float* c1 = acc[nb * 2 + 1];
            asm volatile("mma.sync.aligned.m16n8k16.row.col.f32.f16.f16.f32 "
                         "{%0,%1,%2,%3}, {%4,%5,%6,%7}, {%8,%9}, {%0,%1,%2,%3};"
                         : "+f"(c0[0]), "+f"(c0[1]), "+f"(c0[2]), "+f"(c0[3])
                         : "r"(a0), "r"(a1), "r"(a2), "r"(a3), "r"(b0), "r"(b1));
            asm volatile("mma.sync.aligned.m16n8k16.row.col.f32.f16.f16.f32 "
                         "{%0,%1,%2,%3}, {%4,%5,%6,%7}, {%8,%9}, {%0,%1,%2,%3};"
                         : "+f"(c1[0]), "+f"(c1[1]), "+f"(c1[2]), "+f"(c1[3])
                         : "r"(a0), "r"(a1), "r"(a2), "r"(a3), "r"(b2), "r"(b3));
        }
    }

    // epilogue: scale by dis[row], store fp16
    int gid  = lane >> 2;         // 0..7
    int tid4 = lane & 3;
    int r1 = row0 + warp * 16 + gid;
    int r2 = r1 + 8;
    float d1 = (r1 < N_NODES) ? g_dis[r1] : 0.f;
    float d2 = (r2 < N_NODES) ? g_dis[r2] : 0.f;
    #pragma unroll
    for (int nt = 0; nt < 16; nt++) {
        int col = nt * 8 + tid4 * 2;
        if (r1 < N_NODES)
            *(__half2*)&OUT[r1 * FDIM + col] = __floats2half2_rn(acc[nt][0] * d1, acc[nt][1] * d1);
        if (r2 < N_NODES)
            *(__half2*)&OUT[r2 * FDIM + col] = __floats2half2_rn(acc[nt][2] * d2, acc[nt][3] * d2);
    }
}

// ---------------- aggregation: H[n] = act(dis[n]*(sum g[src] + g[n]) + b) ----------------
__device__ __forceinline__ float4 cvt_h4(uint2 raw) {
    __half2 h0 = *(__half2*)&raw.x;
    __half2 h1 = *(__half2*)&raw.y;
    float2 a = __half22float2(h0);
    float2 b = __half22float2(h1);
    return make_float4(a.x, a.y, b.x, b.y);
}

__global__ __launch_bounds__(256) void k_agg(const __half* __restrict__ Gm,
                                             const float* __restrict__ bias,
                                             __half* __restrict__ H16,
                                             float* __restrict__ Hf,
                                             int relu) {
    int warp = (blockIdx.x * blockDim.x + threadIdx.x) >> 5;
    int lane = threadIdx.x & 31;
    if (warp >= N_NODES) return;
    int n = warp;
    int deg = g_deg[n];
    if (deg > MAXD) deg = MAXD;
    const uint2* G2 = (const uint2*)Gm;           // row = 32 x uint2
    const int* bk = g_bucket + n * MAXD;

    float4 s4 = cvt_h4(G2[n * 32 + lane]);        // self contribution
    float ax = s4.x, ay = s4.y, az = s4.z, aw = s4.w;

    int i = 0;
    for (; i + 4 <= deg; i += 4) {
        int s0 = bk[i + 0];
        int s1 = bk[i + 1];
        int s2 = bk[i + 2];
        int s3 = bk[i + 3];
        float4 v0 = cvt_h4(G2[s0 * 32 + lane]);
        float4 v1 = cvt_h4(G2[s1 * 32 + lane]);
        float4 v2 = cvt_h4(G2[s2 * 32 + lane]);
        float4 v3 = cvt_h4(G2[s3 * 32 + lane]);
        ax += v0.x + v1.x + v2.x + v3.x;
        ay += v0.y + v1.y + v2.y + v3.y;
        az += v0.z + v1.z + v2.z + v3.z;
        aw += v0.w + v1.w + v2.w + v3.w;
    }
    for (; i < deg; i++) {
        float4 v = cvt_h4(G2[bk[i] * 32 + lane]);
        ax += v.x; ay += v.y; az += v.z; aw += v.w;
    }

    float d = g_dis[n];
    float4 bb = ((const float4*)bias)[lane];
    float ox = d * ax + bb.x;
    float oy = d * ay + bb.y;
    float oz = d * az + bb.z;
    float ow = d * aw + bb.w;
    if (relu) {
        ox = fmaxf(ox, 0.f); oy = fmaxf(oy, 0.f);
        oz = fmaxf(oz, 0.f); ow = fmaxf(ow, 0.f);
        uint2 o;
        *(__half2*)&o.x = __floats2half2_rn(ox, oy);
        *(__half2*)&o.y = __floats2half2_rn(oz, ow);
        ((uint2*)H16)[n * 32 + lane] = o;
    } else {
        ((float4*)Hf)[n * 32 + lane] = make_float4(ox, oy, oz, ow);
    }
}

// ---------------- mean pool: one block per graph ----------------
__global__ void k_pool(const float* __restrict__ H, float* __restrict__ out) {
    int g = blockIdx.x;
    int t = threadIdx.x;   // 128 threads = feature dims
    int s = g_starts[g];
    int e = g_starts[g + 1];
    float acc = 0.f;
    for (int n = s; n < e; n++) acc += H[n * FDIM + t];
    float cnt = (float)(e - s);
    out[g * FDIM + t] = acc / fmaxf(cnt, 1.0f);
}

// ---------------- launch ----------------
extern "C" void kernel_launch(void* const* d_in, const int* in_sizes, int n_in,
                              void* d_out, int out_size) {
    const float* x     = (const float*)d_in[0];
    const int*   ei    = (const int*)d_in[1];
    const int*   batch = (const int*)d_in[2];
    const float* W0    = (const float*)d_in[3];
    const float* b0    = (const float*)d_in[4];
    const float* W1    = (const float*)d_in[5];
    const float* b1    = (const float*)d_in[6];
    const float* W2    = (const float*)d_in[7];
    const float* b2    = (const float*)d_in[8];
    float* out = (float*)d_out;

    const int* src = ei;
    const int* dst = ei + N_EDGES;

    __half* xh;  cudaGetSymbolAddress((void**)&xh,  g_xh);
    __half* wh0; cudaGetSymbolAddress((void**)&wh0, g_wh0);
    __half* wh1; cudaGetSymbolAddress((void**)&wh1, g_wh1);
    __half* wh2; cudaGetSymbolAddress((void**)&wh2, g_wh2);
    __half* gbuf; cudaGetSymbolAddress((void**)&gbuf, g_gbuf);
    __half* h16;  cudaGetSymbolAddress((void**)&h16,  g_h16);
    float*  hbuf; cudaGetSymbolAddress((void**)&hbuf, g_hbuf);

    // CSR build + dis + graph starts
    k_zero_deg<<<(N_NODES + 255) / 256, 256>>>();
    k_bucket4<<<(N_EDGES / 4 + 255) / 256, 256>>>(src, dst);
    k_dis_starts<<<(N_NODES + 255) / 256, 256>>>(batch);

    // fp16 conversions
    k_f2h<<<(N_NODES * FDIM / 4 + 255) / 256, 256>>>(x,  xh,  N_NODES * FDIM / 4);
    k_f2h<<<(FDIM * FDIM / 4 + 255) / 256, 256>>>(W0, wh0, FDIM * FDIM / 4);
    k_f2h<<<(FDIM * FDIM / 4 + 255) / 256, 256>>>(W1, wh1, FDIM * FDIM / 4);
    k_f2h<<<(FDIM * FDIM / 4 + 255) / 256, 256>>>(W2, wh2, FDIM * FDIM / 4);

    const int gemm_grid = (N_NODES + 63) / 64;           // 157
    const int agg_grid  = (N_NODES * 32 + 255) / 256;

    // layer 0
    k_gemm<<<gemm_grid, 128>>>(xh, wh0, gbuf);
    k_agg<<<agg_grid, 256>>>(gbuf, b0, h16, hbuf, 1);
    // layer 1
    k_gemm<<<gemm_grid, 128>>>(h16, wh1, gbuf);
    k_agg<<<agg_grid, 256>>>(gbuf, b1, h16, hbuf, 1);
    // layer 2
    k_gemm<<<gemm_grid, 128>>>(h16, wh2, gbuf);
    k_agg<<<agg_grid, 256>>>(gbuf, b2, h16, hbuf, 0);

    // mean pool
    k_pool<<<NGRAPH, FDIM>>>(hbuf, out);
}

// round 4
// speedup vs baseline: 1.4602x; 1.4602x over previous
#include <cuda_runtime.h>
#include <cuda_fp16.h>
#include <cstdint>

#define N_NODES 10000
#define N_EDGES 640000
#define FDIM    128
#define NGRAPH  64
#define MAXD    192

// ---------------- device scratch (no allocation allowed) ----------------
__device__ int    g_deg[N_NODES];
__device__ float  g_dis[N_NODES];
__device__ int    g_bucket[N_NODES * MAXD];      // per-dst neighbor lists
__device__ __half g_gbuf[N_NODES * FDIM];        // GEMM output, dis-prescaled, fp16
__device__ __half g_h16[N_NODES * FDIM];         // agg output fp16 (layers 0,1)
__device__ float  g_hbuf[N_NODES * FDIM];        // agg output fp32 (layer 2)
__device__ int    g_starts[NGRAPH + 1];

// ---------------- one-pass bucket CSR ----------------
__global__ void k_zero_deg() {
    int n = blockIdx.x * blockDim.x + threadIdx.x;
    if (n < N_NODES) g_deg[n] = 0;
}

// 4 edges per thread for atomic MLP
__global__ void k_bucket4(const int* __restrict__ src, const int* __restrict__ dst) {
    int i = blockIdx.x * blockDim.x + threadIdx.x;
    if (i >= N_EDGES / 4) return;
    int4 s = ((const int4*)src)[i];
    int4 d = ((const int4*)dst)[i];
    int p;
    p = atomicAdd(&g_deg[d.x], 1); if (p < MAXD) g_bucket[d.x * MAXD + p] = s.x;
    p = atomicAdd(&g_deg[d.y], 1); if (p < MAXD) g_bucket[d.y * MAXD + p] = s.y;
    p = atomicAdd(&g_deg[d.z], 1); if (p < MAXD) g_bucket[d.z * MAXD + p] = s.z;
    p = atomicAdd(&g_deg[d.w], 1); if (p < MAXD) g_bucket[d.w * MAXD + p] = s.w;
}

// dis = rsqrt(deg+1); also graph-boundary starts (batch is sorted)
__global__ void k_dis_starts(const int* __restrict__ batch) {
    int n = blockIdx.x * blockDim.x + threadIdx.x;
    if (n >= N_NODES) return;
    g_dis[n] = rsqrtf((float)g_deg[n] + 1.0f);
    int b1 = batch[n];
    if (n == 0) {
        for (int b = 0; b <= b1; b++) g_starts[b] = 0;
    } else {
        int b0 = batch[n - 1];
        for (int b = b0 + 1; b <= b1; b++) g_starts[b] = n;
    }
    if (n == N_NODES - 1) {
        for (int b = b1 + 1; b <= NGRAPH; b++) g_starts[b] = N_NODES;
    }
}

// ---------------- HMMA GEMM: OUT[n][:] = half( dis[n] * (A[n][:] @ W) ) ----------------
// 256 threads (8 warps), 64 rows x 128 cols per block.
// Warp w: rows (w>>1)*16, cols (w&1)*64. W is fp32 in gmem, converted to fp16
// during smem staging. A is fp32 (layer 0) or fp16 (layers 1,2), converted likewise.
__device__ __forceinline__ int swz_g(int row, int col8) {   // 8-half group start
    return row * FDIM + ((col8 ^ (row & 7)) << 3);
}
__device__ __forceinline__ int swz_h(int row, int col) {    // arbitrary half index (col%4==0 ok)
    return row * FDIM + (((col >> 3) ^ (row & 7)) << 3) + (col & 7);
}

template<bool F32IN>
__global__ __launch_bounds__(256) void k_gemm(const void* __restrict__ Ap,
                                              const float* __restrict__ Wf,
                                              __half* __restrict__ OUT) {
    __shared__ __half Wsh[FDIM * FDIM];   // 32 KB
    __shared__ __half Ash[64 * FDIM];     // 16 KB
    int tid  = threadIdx.x;
    int lane = tid & 31;
    int warp = tid >> 5;
    int row0 = blockIdx.x * 64;

    // stage W: 4096 float4 chunks, 16 per thread, convert fp32->fp16
    #pragma unroll
    for (int i = 0; i < 16; i++) {
        int idx = tid + i * 256;            // 0..4095
        int r   = idx >> 5;
        int c   = (idx & 31) * 4;
        float4 v = ((const float4*)Wf)[idx];
        uint2 h;
        *(__half2*)&h.x = __floats2half2_rn(v.x, v.y);
        *(__half2*)&h.y = __floats2half2_rn(v.z, v.w);
        *(uint2*)&Wsh[swz_h(r, c)] = h;
    }
    // stage A tile (zero-fill OOB rows)
    if (F32IN) {
        const float* A = (const float*)Ap;
        #pragma unroll
        for (int i = 0; i < 8; i++) {
            int idx = tid + i * 256;        // 0..2047
            int r   = idx >> 5;
            int c   = (idx & 31) * 4;
            int gr  = row0 + r;
            float4 v = make_float4(0.f, 0.f, 0.f, 0.f);
            if (gr < N_NODES) v = *(const float4*)&A[gr * FDIM + c];
            uint2 h;
            *(__half2*)&h.x = __floats2half2_rn(v.x, v.y);
            *(__half2*)&h.y = __floats2half2_rn(v.z, v.w);
            *(uint2*)&Ash[swz_h(r, c)] = h;
        }
    } else {
        const __half* A = (const __half*)Ap;
        #pragma unroll
        for (int i = 0; i < 4; i++) {
            int idx = tid + i * 256;        // 0..1023
            int r   = idx >> 4;
            int c8  = idx & 15;
            int gr  = row0 + r;
            uint4 v = make_uint4(0, 0, 0, 0);
            if (gr < N_NODES) v = ((const uint4*)A)[gr * 16 + c8];
            *(uint4*)&Ash[swz_g(r, c8)] = v;
        }
    }
    __syncthreads();

    int rw = (warp >> 1) * 16;       // warp row offset in tile
    int cw = (warp & 1) * 64;        // warp col offset

    float acc[8][4];
    #pragma unroll
    for (int nt = 0; nt < 8; nt++)
        #pragma unroll
        for (int c = 0; c < 4; c++) acc[nt][c] = 0.f;

    int m  = lane >> 3;      // ldmatrix sub-matrix id 0..3
    int l7 = lane & 7;

    #pragma unroll
    for (int kk = 0; kk < 8; kk++) {
        int k0 = kk * 16;
        uint32_t a0, a1, a2, a3;
        {
            int rl = rw + ((m & 1) << 3) + l7;
            int c8 = (k0 >> 3) + (m >> 1);
            uint32_t addr = (uint32_t)__cvta_generic_to_shared(&Ash[swz_g(rl, c8)]);
            asm volatile("ldmatrix.sync.aligned.m8n8.x4.shared.b16 {%0,%1,%2,%3}, [%4];"
                         : "=r"(a0), "=r"(a1), "=r"(a2), "=r"(a3) : "r"(addr));
        }
        #pragma unroll
        for (int nb = 0; nb < 4; nb++) {
            int n0 = cw + nb * 16;
            uint32_t b0, b1, b2, b3;
            {
                int rl = k0 + ((m & 1) << 3) + l7;
                int c8 = (n0 >> 3) + (m >> 1);
                uint32_t addr = (uint32_t)__cvta_generic_to_shared(&Wsh[swz_g(rl, c8)]);
                asm volatile("ldmatrix.sync.aligned.m8n8.x4.trans.shared.b16 {%0,%1,%2,%3}, [%4];"
                             : "=r"(b0), "=r"(b1), "=r"(b2), "=r"(b3) : "r"(addr));
            }
            float* c0 = acc[nb * 2];
            float* c1 = acc[nb * 2 + 1];
            asm volatile("mma.sync.aligned.m16n8k16.row.col.f32.f16.f16.f32 "
                         "{%0,%1,%2,%3}, {%4,%5,%6,%7}, {%8,%9}, {%0,%1,%2,%3};"
                         : "+f"(c0[0]), "+f"(c0[1]), "+f"(c0[2]), "+f"(c0[3])
                         : "r"(a0), "r"(a1), "r"(a2), "r"(a3), "r"(b0), "r"(b1));
            asm volatile("mma.sync.aligned.m16n8k16.row.col.f32.f16.f16.f32 "
                         "{%0,%1,%2,%3}, {%4,%5,%6,%7}, {%8,%9}, {%0,%1,%2,%3};"
                         : "+f"(c1[0]), "+f"(c1[1]), "+f"(c1[2]), "+f"(c1[3])
                         : "r"(a0), "r"(a1), "r"(a2), "r"(a3), "r"(b2), "r"(b3));
        }
    }

    // epilogue: scale by dis[row], store fp16
    int gid  = lane >> 2;         // 0..7
    int tid4 = lane & 3;
    int r1 = row0 + rw + gid;
    int r2 = r1 + 8;
    float d1 = (r1 < N_NODES) ? g_dis[r1] : 0.f;
    float d2 = (r2 < N_NODES) ? g_dis[r2] : 0.f;
    #pragma unroll
    for (int nt = 0; nt < 8; nt++) {
        int col = cw + nt * 8 + tid4 * 2;
        if (r1 < N_NODES)
            *(__half2*)&OUT[r1 * FDIM + col] = __floats2half2_rn(acc[nt][0] * d1, acc[nt][1] * d1);
        if (r2 < N_NODES)
            *(__half2*)&OUT[r2 * FDIM + col] = __floats2half2_rn(acc[nt][2] * d2, acc[nt][3] * d2);
    }
}

// ---------------- aggregation: H[n] = act(dis[n]*(sum g[src] + g[n]) + b) ----------------
__device__ __forceinline__ float4 cvt_h4(uint2 raw) {
    __half2 h0 = *(__half2*)&raw.x;
    __half2 h1 = *(__half2*)&raw.y;
    float2 a = __half22float2(h0);
    float2 b = __half22float2(h1);
    return make_float4(a.x, a.y, b.x, b.y);
}

__global__ __launch_bounds__(256) void k_agg(const __half* __restrict__ Gm,
                                             const float* __restrict__ bias,
                                             __half* __restrict__ H16,
                                             float* __restrict__ Hf,
                                             int relu) {
    int warp = (blockIdx.x * blockDim.x + threadIdx.x) >> 5;
    int lane = threadIdx.x & 31;
    if (warp >= N_NODES) return;
    int n = warp;
    int deg = g_deg[n];
    if (deg > MAXD) deg = MAXD;
    const uint2* G2 = (const uint2*)Gm;           // row = 32 x uint2
    const int* bk = g_bucket + n * MAXD;

    float4 s4 = cvt_h4(G2[n * 32 + lane]);        // self contribution
    float ax = s4.x, ay = s4.y, az = s4.z, aw = s4.w;

    int i = 0;
    for (; i + 4 <= deg; i += 4) {
        int s0 = bk[i + 0];
        int s1 = bk[i + 1];
        int s2 = bk[i + 2];
        int s3 = bk[i + 3];
        float4 v0 = cvt_h4(G2[s0 * 32 + lane]);
        float4 v1 = cvt_h4(G2[s1 * 32 + lane]);
        float4 v2 = cvt_h4(G2[s2 * 32 + lane]);
        float4 v3 = cvt_h4(G2[s3 * 32 + lane]);
        ax += v0.x + v1.x + v2.x + v3.x;
        ay += v0.y + v1.y + v2.y + v3.y;
        az += v0.z + v1.z + v2.z + v3.z;
        aw += v0.w + v1.w + v2.w + v3.w;
    }
    for (; i < deg; i++) {
        float4 v = cvt_h4(G2[bk[i] * 32 + lane]);
        ax += v.x; ay += v.y; az += v.z; aw += v.w;
    }

    float d = g_dis[n];
    float4 bb = ((const float4*)bias)[lane];
    float ox = d * ax + bb.x;
    float oy = d * ay + bb.y;
    float oz = d * az + bb.z;
    float ow = d * aw + bb.w;
    if (relu) {
        ox = fmaxf(ox, 0.f); oy = fmaxf(oy, 0.f);
        oz = fmaxf(oz, 0.f); ow = fmaxf(ow, 0.f);
        uint2 o;
        *(__half2*)&o.x = __floats2half2_rn(ox, oy);
        *(__half2*)&o.y = __floats2half2_rn(oz, ow);
        ((uint2*)H16)[n * 32 + lane] = o;
    } else {
        ((float4*)Hf)[n * 32 + lane] = make_float4(ox, oy, oz, ow);
    }
}

// ---------------- mean pool: one block per graph ----------------
__global__ void k_pool(const float* __restrict__ H, float* __restrict__ out) {
    int g = blockIdx.x;
    int t = threadIdx.x;   // 128 threads = feature dims
    int s = g_starts[g];
    int e = g_starts[g + 1];
    float acc = 0.f;
    for (int n = s; n < e; n++) acc += H[n * FDIM + t];
    float cnt = (float)(e - s);
    out[g * FDIM + t] = acc / fmaxf(cnt, 1.0f);
}

// ---------------- launch ----------------
extern "C" void kernel_launch(void* const* d_in, const int* in_sizes, int n_in,
                              void* d_out, int out_size) {
    const float* x     = (const float*)d_in[0];
    const int*   ei    = (const int*)d_in[1];
    const int*   batch = (const int*)d_in[2];
    const float* W0    = (const float*)d_in[3];
    const float* b0    = (const float*)d_in[4];
    const float* W1    = (const float*)d_in[5];
    const float* b1    = (const float*)d_in[6];
    const float* W2    = (const float*)d_in[7];
    const float* b2    = (const float*)d_in[8];
    float* out = (float*)d_out;

    const int* src = ei;
    const int* dst = ei + N_EDGES;

    __half* gbuf; cudaGetSymbolAddress((void**)&gbuf, g_gbuf);
    __half* h16;  cudaGetSymbolAddress((void**)&h16,  g_h16);
    float*  hbuf; cudaGetSymbolAddress((void**)&hbuf, g_hbuf);

    // CSR build + dis + graph starts
    k_zero_deg<<<(N_NODES + 255) / 256, 256>>>();
    k_bucket4<<<(N_EDGES / 4 + 255) / 256, 256>>>(src, dst);
    k_dis_starts<<<(N_NODES + 255) / 256, 256>>>(batch);

    const int gemm_grid = (N_NODES + 63) / 64;           // 157
    const int agg_grid  = (N_NODES * 32 + 255) / 256;

    // layer 0 (fp32 X input, fused conversion)
    k_gemm<true><<<gemm_grid, 256>>>((const void*)x, W0, gbuf);
    k_agg<<<agg_grid, 256>>>(gbuf, b0, h16, hbuf, 1);
    // layer 1
    k_gemm<false><<<gemm_grid, 256>>>((const void*)h16, W1, gbuf);
    k_agg<<<agg_grid, 256>>>(gbuf, b1, h16, hbuf, 1);
    // layer 2
    k_gemm<false><<<gemm_grid, 256>>>((const void*)h16, W2, gbuf);
    k_agg<<<agg_grid, 256>>>(gbuf, b2, h16, hbuf, 0);

    // mean pool
    k_pool<<<NGRAPH, FDIM>>>(hbuf, out);
}

// round 5
// speedup vs baseline: 1.4814x; 1.0145x over previous
#include <cuda_runtime.h>
#include <cuda_fp16.h>
#include <cstdint>

#define N_NODES 10000
#define N_EDGES 640000
#define FDIM    128
#define NGRAPH  64
#define MAXD    192

// ---------------- device scratch (no allocation allowed) ----------------
__device__ int    g_deg[N_NODES];
__device__ float  g_dis[N_NODES];
__device__ int    g_bucket[N_NODES * MAXD];      // per-dst neighbor lists
__device__ __half g_gbuf[N_NODES * FDIM];        // GEMM output, dis-prescaled, fp16
__device__ __half g_h16[N_NODES * FDIM];         // agg output fp16 (layers 0,1)
__device__ float  g_hbuf[N_NODES * FDIM];        // agg output fp32 (layer 2)
__device__ int    g_starts[NGRAPH + 1];

// ---------------- one-pass bucket CSR: 8 edges per thread ----------------
__global__ void k_bucket8(const int* __restrict__ src, const int* __restrict__ dst) {
    int i = blockIdx.x * blockDim.x + threadIdx.x;
    if (i >= N_EDGES / 8) return;
    int4 s0 = ((const int4*)src)[i * 2 + 0];
    int4 s1 = ((const int4*)src)[i * 2 + 1];
    int4 d0 = ((const int4*)dst)[i * 2 + 0];
    int4 d1 = ((const int4*)dst)[i * 2 + 1];
    int p;
    p = atomicAdd(&g_deg[d0.x], 1); if (p < MAXD) g_bucket[d0.x * MAXD + p] = s0.x;
    p = atomicAdd(&g_deg[d0.y], 1); if (p < MAXD) g_bucket[d0.y * MAXD + p] = s0.y;
    p = atomicAdd(&g_deg[d0.z], 1); if (p < MAXD) g_bucket[d0.z * MAXD + p] = s0.z;
    p = atomicAdd(&g_deg[d0.w], 1); if (p < MAXD) g_bucket[d0.w * MAXD + p] = s0.w;
    p = atomicAdd(&g_deg[d1.x], 1); if (p < MAXD) g_bucket[d1.x * MAXD + p] = s1.x;
    p = atomicAdd(&g_deg[d1.y], 1); if (p < MAXD) g_bucket[d1.y * MAXD + p] = s1.y;
    p = atomicAdd(&g_deg[d1.z], 1); if (p < MAXD) g_bucket[d1.z * MAXD + p] = s1.z;
    p = atomicAdd(&g_deg[d1.w], 1); if (p < MAXD) g_bucket[d1.w * MAXD + p] = s1.w;
}

// dis = rsqrt(deg+1); also graph-boundary starts (batch is sorted)
__global__ void k_dis_starts(const int* __restrict__ batch) {
    int n = blockIdx.x * blockDim.x + threadIdx.x;
    if (n >= N_NODES) return;
    g_dis[n] = rsqrtf((float)g_deg[n] + 1.0f);
    int b1 = batch[n];
    if (n == 0) {
        for (int b = 0; b <= b1; b++) g_starts[b] = 0;
    } else {
        int b0 = batch[n - 1];
        for (int b = b0 + 1; b <= b1; b++) g_starts[b] = n;
    }
    if (n == N_NODES - 1) {
        for (int b = b1 + 1; b <= NGRAPH; b++) g_starts[b] = N_NODES;
    }
}

// ---------------- HMMA GEMM: OUT[n][:] = half( dis[n] * (A[n][:] @ W) ) ----------------
// 512 threads (16 warps), 64 rows x 128 cols per block.
// Warp w: rows (w>>2)*16, cols (w&3)*32. W fp32 -> fp16 during smem staging.
__device__ __forceinline__ int swz_g(int row, int col8) {   // 8-half group start
    return row * FDIM + ((col8 ^ (row & 7)) << 3);
}
__device__ __forceinline__ int swz_h(int row, int col) {    // half index, col%4==0
    return row * FDIM + (((col >> 3) ^ (row & 7)) << 3) + (col & 7);
}

template<bool F32IN>
__global__ __launch_bounds__(512) void k_gemm(const void* __restrict__ Ap,
                                              const float* __restrict__ Wf,
                                              __half* __restrict__ OUT) {
    __shared__ __half Wsh[FDIM * FDIM];   // 32 KB
    __shared__ __half Ash[64 * FDIM];     // 16 KB
    int tid  = threadIdx.x;
    int lane = tid & 31;
    int warp = tid >> 5;
    int row0 = blockIdx.x * 64;

    // stage W: 4096 float4, 8 per thread, convert fp32->fp16
    #pragma unroll
    for (int i = 0; i < 8; i++) {
        int idx = tid + i * 512;            // 0..4095
        int r   = idx >> 5;
        int c   = (idx & 31) * 4;
        float4 v = ((const float4*)Wf)[idx];
        uint2 h;
        *(__half2*)&h.x = __floats2half2_rn(v.x, v.y);
        *(__half2*)&h.y = __floats2half2_rn(v.z, v.w);
        *(uint2*)&Wsh[swz_h(r, c)] = h;
    }
    // stage A tile (zero-fill OOB rows)
    if (F32IN) {
        const float* A = (const float*)Ap;
        #pragma unroll
        for (int i = 0; i < 4; i++) {
            int idx = tid + i * 512;        // 0..2047
            int r   = idx >> 5;
            int c   = (idx & 31) * 4;
            int gr  = row0 + r;
            float4 v = make_float4(0.f, 0.f, 0.f, 0.f);
            if (gr < N_NODES) v = *(const float4*)&A[gr * FDIM + c];
            uint2 h;
            *(__half2*)&h.x = __floats2half2_rn(v.x, v.y);
            *(__half2*)&h.y = __floats2half2_rn(v.z, v.w);
            *(uint2*)&Ash[swz_h(r, c)] = h;
        }
    } else {
        const __half* A = (const __half*)Ap;
        #pragma unroll
        for (int i = 0; i < 2; i++) {
            int idx = tid + i * 512;        // 0..1023
            int r   = idx >> 4;
            int c8  = idx & 15;
            int gr  = row0 + r;
            uint4 v = make_uint4(0, 0, 0, 0);
            if (gr < N_NODES) v = ((const uint4*)A)[gr * 16 + c8];
            *(uint4*)&Ash[swz_g(r, c8)] = v;
        }
    }
    __syncthreads();

    int rw = (warp >> 2) * 16;       // warp row offset in tile
    int cw = (warp & 3) * 32;        // warp col offset

    float acc[4][4];
    #pragma unroll
    for (int nt = 0; nt < 4; nt++)
        #pragma unroll
        for (int c = 0; c < 4; c++) acc[nt][c] = 0.f;

    int m  = lane >> 3;      // ldmatrix sub-matrix id 0..3
    int l7 = lane & 7;

    #pragma unroll
    for (int kk = 0; kk < 8; kk++) {
        int k0 = kk * 16;
        uint32_t a0, a1, a2, a3;
        {
            int rl = rw + ((m & 1) << 3) + l7;
            int c8 = (k0 >> 3) + (m >> 1);
            uint32_t addr = (uint32_t)__cvta_generic_to_shared(&Ash[swz_g(rl, c8)]);
            asm volatile("ldmatrix.sync.aligned.m8n8.x4.shared.b16 {%0,%1,%2,%3}, [%4];"
                         : "=r"(a0), "=r"(a1), "=r"(a2), "=r"(a3) : "r"(addr));
        }
        #pragma unroll
        for (int nb = 0; nb < 2; nb++) {
            int n0 = cw + nb * 16;
            uint32_t b0, b1, b2, b3;
            {
                int rl = k0 + ((m & 1) << 3) + l7;
                int c8 = (n0 >> 3) + (m >> 1);
                uint32_t addr = (uint32_t)__cvta_generic_to_shared(&Wsh[swz_g(rl, c8)]);
                asm volatile("ldmatrix.sync.aligned.m8n8.x4.trans.shared.b16 {%0,%1,%2,%3}, [%4];"
                             : "=r"(b0), "=r"(b1), "=r"(b2), "=r"(b3) : "r"(addr));
            }
            float* c0 = acc[nb * 2];
            float* c1 = acc[nb * 2 + 1];
            asm volatile("mma.sync.aligned.m16n8k16.row.col.f32.f16.f16.f32 "
                         "{%0,%1,%2,%3}, {%4,%5,%6,%7}, {%8,%9}, {%0,%1,%2,%3};"
                         : "+f"(c0[0]), "+f"(c0[1]), "+f"(c0[2]), "+f"(c0[3])
                         : "r"(a0), "r"(a1), "r"(a2), "r"(a3), "r"(b0), "r"(b1));
            asm volatile("mma.sync.aligned.m16n8k16.row.col.f32.f16.f16.f32 "
                         "{%0,%1,%2,%3}, {%4,%5,%6,%7}, {%8,%9}, {%0,%1,%2,%3};"
                         : "+f"(c1[0]), "+f"(c1[1]), "+f"(c1[2]), "+f"(c1[3])
                         : "r"(a0), "r"(a1), "r"(a2), "r"(a3), "r"(b2), "r"(b3));
        }
    }

    // epilogue: scale by dis[row], store fp16
    int gid  = lane >> 2;         // 0..7
    int tid4 = lane & 3;
    int r1 = row0 + rw + gid;
    int r2 = r1 + 8;
    float d1 = (r1 < N_NODES) ? g_dis[r1] : 0.f;
    float d2 = (r2 < N_NODES) ? g_dis[r2] : 0.f;
    #pragma unroll
    for (int nt = 0; nt < 4; nt++) {
        int col = cw + nt * 8 + tid4 * 2;
        if (r1 < N_NODES)
            *(__half2*)&OUT[r1 * FDIM + col] = __floats2half2_rn(acc[nt][0] * d1, acc[nt][1] * d1);
        if (r2 < N_NODES)
            *(__half2*)&OUT[r2 * FDIM + col] = __floats2half2_rn(acc[nt][2] * d2, acc[nt][3] * d2);
    }
}

// ---------------- aggregation: H[n] = act(dis[n]*(sum g[src] + g[n]) + b) ----------------
__device__ __forceinline__ float4 cvt_h4(uint2 raw) {
    __half2 h0 = *(__half2*)&raw.x;
    __half2 h1 = *(__half2*)&raw.y;
    float2 a = __half22float2(h0);
    float2 b = __half22float2(h1);
    return make_float4(a.x, a.y, b.x, b.y);
}

__global__ __launch_bounds__(256) void k_agg(const __half* __restrict__ Gm,
                                             const float* __restrict__ bias,
                                             __half* __restrict__ H16,
                                             float* __restrict__ Hf,
                                             int relu) {
    int warp = (blockIdx.x * blockDim.x + threadIdx.x) >> 5;
    int lane = threadIdx.x & 31;
    if (warp >= N_NODES) return;
    int n = warp;
    int deg = g_deg[n];
    if (deg > MAXD) deg = MAXD;
    const uint2* G2 = (const uint2*)Gm;           // row = 32 x uint2
    const int* bk = g_bucket + n * MAXD;

    float4 s4 = cvt_h4(G2[n * 32 + lane]);        // self contribution
    float ax = s4.x, ay = s4.y, az = s4.z, aw = s4.w;

    int i = 0;
    for (; i + 4 <= deg; i += 4) {
        int s0 = bk[i + 0];
        int s1 = bk[i + 1];
        int s2 = bk[i + 2];
        int s3 = bk[i + 3];
        float4 v0 = cvt_h4(G2[s0 * 32 + lane]);
        float4 v1 = cvt_h4(G2[s1 * 32 + lane]);
        float4 v2 = cvt_h4(G2[s2 * 32 + lane]);
        float4 v3 = cvt_h4(G2[s3 * 32 + lane]);
        ax += v0.x + v1.x + v2.x + v3.x;
        ay += v0.y + v1.y + v2.y + v3.y;
        az += v0.z + v1.z + v2.z + v3.z;
        aw += v0.w + v1.w + v2.w + v3.w;
    }
    for (; i < deg; i++) {
        float4 v = cvt_h4(G2[bk[i] * 32 + lane]);
        ax += v.x; ay += v.y; az += v.z; aw += v.w;
    }

    float d = g_dis[n];
    float4 bb = ((const float4*)bias)[lane];
    float ox = d * ax + bb.x;
    float oy = d * ay + bb.y;
    float oz = d * az + bb.z;
    float ow = d * aw + bb.w;
    if (relu) {
        ox = fmaxf(ox, 0.f); oy = fmaxf(oy, 0.f);
        oz = fmaxf(oz, 0.f); ow = fmaxf(ow, 0.f);
        uint2 o;
        *(__half2*)&o.x = __floats2half2_rn(ox, oy);
        *(__half2*)&o.y = __floats2half2_rn(oz, ow);
        ((uint2*)H16)[n * 32 + lane] = o;
    } else {
        ((float4*)Hf)[n * 32 + lane] = make_float4(ox, oy, oz, ow);
    }
}

// ---------------- mean pool: one block per graph, 4 warps split rows ----------------
__global__ __launch_bounds__(128) void k_pool(const float* __restrict__ H,
                                              float* __restrict__ out) {
    __shared__ float red[4][FDIM];
    int g    = blockIdx.x;
    int lane = threadIdx.x & 31;
    int warp = threadIdx.x >> 5;
    int s = g_starts[g];
    int e = g_starts[g + 1];
    float4 acc = make_float4(0.f, 0.f, 0.f, 0.f);
    for (int n = s + warp; n < e; n += 4) {
        float4 v = ((const float4*)H)[n * 32 + lane];
        acc.x += v.x; acc.y += v.y; acc.z += v.z; acc.w += v.w;
    }
    *(float4*)&red[warp][lane * 4] = acc;
    __syncthreads();
    int t = threadIdx.x;   // 0..127 = feature dim
    float sum = red[0][t] + red[1][t] + red[2][t] + red[3][t];
    float cnt = (float)(e - s);
    out[g * FDIM + t] = sum / fmaxf(cnt, 1.0f);
}

// ---------------- launch ----------------
extern "C" void kernel_launch(void* const* d_in, const int* in_sizes, int n_in,
                              void* d_out, int out_size) {
    const float* x     = (const float*)d_in[0];
    const int*   ei    = (const int*)d_in[1];
    const int*   batch = (const int*)d_in[2];
    const float* W0    = (const float*)d_in[3];
    const float* b0    = (const float*)d_in[4];
    const float* W1    = (const float*)d_in[5];
    const float* b1    = (const float*)d_in[6];
    const float* W2    = (const float*)d_in[7];
    const float* b2    = (const float*)d_in[8];
    float* out = (float*)d_out;

    const int* src = ei;
    const int* dst = ei + N_EDGES;

    int*    dg;   cudaGetSymbolAddress((void**)&dg,   g_deg);
    __half* gbuf; cudaGetSymbolAddress((void**)&gbuf, g_gbuf);
    __half* h16;  cudaGetSymbolAddress((void**)&h16,  g_h16);
    float*  hbuf; cudaGetSymbolAddress((void**)&hbuf, g_hbuf);

    // CSR build + dis + graph starts
    cudaMemsetAsync(dg, 0, N_NODES * sizeof(int));
    k_bucket8<<<(N_EDGES / 8 + 255) / 256, 256>>>(src, dst);
    k_dis_starts<<<(N_NODES + 255) / 256, 256>>>(batch);

    const int gemm_grid = (N_NODES + 63) / 64;           // 157
    const int agg_grid  = (N_NODES * 32 + 255) / 256;

    // layer 0 (fp32 X input, fused conversion)
    k_gemm<true><<<gemm_grid, 512>>>((const void*)x, W0, gbuf);
    k_agg<<<agg_grid, 256>>>(gbuf, b0, h16, hbuf, 1);
    // layer 1
    k_gemm<false><<<gemm_grid, 512>>>((const void*)h16, W1, gbuf);
    k_agg<<<agg_grid, 256>>>(gbuf, b1, h16, hbuf, 1);
    // layer 2
    k_gemm<false><<<gemm_grid, 512>>>((const void*)h16, W2, gbuf);
    k_agg<<<agg_grid, 256>>>(gbuf, b2, h16, hbuf, 0);

    // mean pool
    k_pool<<<NGRAPH, FDIM>>>(hbuf, out);
}

// round 6
// speedup vs baseline: 1.7052x; 1.1511x over previous
#include <cuda_runtime.h>
#include <cuda_fp16.h>
#include <cstdint>

#define N_NODES 10000
#define N_EDGES 640000
#define FDIM    128
#define NGRAPH  64
#define MAXD    192

// ---------------- device scratch (no allocation allowed) ----------------
__device__ int    g_deg[N_NODES];
__device__ float  g_dis[N_NODES];
__device__ int    g_bucket[N_NODES * MAXD];      // per-dst neighbor lists
__device__ __half g_gbuf[N_NODES * FDIM];        // GEMM output, dis-prescaled, fp16
__device__ __half g_h16[N_NODES * FDIM];         // agg output fp16 (layers 0,1)
__device__ float  g_hbuf[N_NODES * FDIM];        // agg output fp32 (layer 2)
__device__ int    g_starts[NGRAPH + 1];

// ---------------- one-pass bucket CSR: 8 edges per thread ----------------
__global__ void k_bucket8(const int* __restrict__ src, const int* __restrict__ dst) {
    int i = blockIdx.x * blockDim.x + threadIdx.x;
    if (i >= N_EDGES / 8) return;
    int4 s0 = ((const int4*)src)[i * 2 + 0];
    int4 s1 = ((const int4*)src)[i * 2 + 1];
    int4 d0 = ((const int4*)dst)[i * 2 + 0];
    int4 d1 = ((const int4*)dst)[i * 2 + 1];
    int p;
    p = atomicAdd(&g_deg[d0.x], 1); if (p < MAXD) g_bucket[d0.x * MAXD + p] = s0.x;
    p = atomicAdd(&g_deg[d0.y], 1); if (p < MAXD) g_bucket[d0.y * MAXD + p] = s0.y;
    p = atomicAdd(&g_deg[d0.z], 1); if (p < MAXD) g_bucket[d0.z * MAXD + p] = s0.z;
    p = atomicAdd(&g_deg[d0.w], 1); if (p < MAXD) g_bucket[d0.w * MAXD + p] = s0.w;
    p = atomicAdd(&g_deg[d1.x], 1); if (p < MAXD) g_bucket[d1.x * MAXD + p] = s1.x;
    p = atomicAdd(&g_deg[d1.y], 1); if (p < MAXD) g_bucket[d1.y * MAXD + p] = s1.y;
    p = atomicAdd(&g_deg[d1.z], 1); if (p < MAXD) g_bucket[d1.z * MAXD + p] = s1.z;
    p = atomicAdd(&g_deg[d1.w], 1); if (p < MAXD) g_bucket[d1.w * MAXD + p] = s1.w;
}

// dis = rsqrt(deg+1); also graph-boundary starts (batch is sorted)
__global__ void k_dis_starts(const int* __restrict__ batch) {
    int n = blockIdx.x * blockDim.x + threadIdx.x;
    if (n >= N_NODES) return;
    g_dis[n] = rsqrtf((float)g_deg[n] + 1.0f);
    int b1 = batch[n];
    if (n == 0) {
        for (int b = 0; b <= b1; b++) g_starts[b] = 0;
    } else {
        int b0 = batch[n - 1];
        for (int b = b0 + 1; b <= b1; b++) g_starts[b] = n;
    }
    if (n == N_NODES - 1) {
        for (int b = b1 + 1; b <= NGRAPH; b++) g_starts[b] = N_NODES;
    }
}

// ---------------- HMMA GEMM: OUT[n][:] = half( dis[n] * (A[n][:] @ W) ) ----------------
// 512 threads (16 warps), 64 rows x 128 cols per block.
// Warp w: rows (w>>2)*16, cols (w&3)*32. W fp32 -> fp16 during smem staging.
__device__ __forceinline__ int swz_g(int row, int col8) {   // 8-half group start
    return row * FDIM + ((col8 ^ (row & 7)) << 3);
}
__device__ __forceinline__ int swz_h(int row, int col) {    // half index, col%4==0
    return row * FDIM + (((col >> 3) ^ (row & 7)) << 3) + (col & 7);
}

template<bool F32IN>
__global__ __launch_bounds__(512) void k_gemm(const void* __restrict__ Ap,
                                              const float* __restrict__ Wf,
                                              __half* __restrict__ OUT) {
    __shared__ __half Wsh[FDIM * FDIM];   // 32 KB
    __shared__ __half Ash[64 * FDIM];     // 16 KB
    int tid  = threadIdx.x;
    int lane = tid & 31;
    int warp = tid >> 5;
    int row0 = blockIdx.x * 64;

    // stage W: 4096 float4, 8 per thread, convert fp32->fp16
    #pragma unroll
    for (int i = 0; i < 8; i++) {
        int idx = tid + i * 512;            // 0..4095
        int r   = idx >> 5;
        int c   = (idx & 31) * 4;
        float4 v = ((const float4*)Wf)[idx];
        uint2 h;
        *(__half2*)&h.x = __floats2half2_rn(v.x, v.y);
        *(__half2*)&h.y = __floats2half2_rn(v.z, v.w);
        *(uint2*)&Wsh[swz_h(r, c)] = h;
    }
    // stage A tile (zero-fill OOB rows)
    if (F32IN) {
        const float* A = (const float*)Ap;
        #pragma unroll
        for (int i = 0; i < 4; i++) {
            int idx = tid + i * 512;        // 0..2047
            int r   = idx >> 5;
            int c   = (idx & 31) * 4;
            int gr  = row0 + r;
            float4 v = make_float4(0.f, 0.f, 0.f, 0.f);
            if (gr < N_NODES) v = *(const float4*)&A[gr * FDIM + c];
            uint2 h;
            *(__half2*)&h.x = __floats2half2_rn(v.x, v.y);
            *(__half2*)&h.y = __floats2half2_rn(v.z, v.w);
            *(uint2*)&Ash[swz_h(r, c)] = h;
        }
    } else {
        const __half* A = (const __half*)Ap;
        #pragma unroll
        for (int i = 0; i < 2; i++) {
            int idx = tid + i * 512;        // 0..1023
            int r   = idx >> 4;
            int c8  = idx & 15;
            int gr  = row0 + r;
            uint4 v = make_uint4(0, 0, 0, 0);
            if (gr < N_NODES) v = ((const uint4*)A)[gr * 16 + c8];
            *(uint4*)&Ash[swz_g(r, c8)] = v;
        }
    }
    __syncthreads();

    int rw = (warp >> 2) * 16;       // warp row offset in tile
    int cw = (warp & 3) * 32;        // warp col offset

    float acc[4][4];
    #pragma unroll
    for (int nt = 0; nt < 4; nt++)
        #pragma unroll
        for (int c = 0; c < 4; c++) acc[nt][c] = 0.f;

    int m  = lane >> 3;      // ldmatrix sub-matrix id 0..3
    int l7 = lane & 7;

    #pragma unroll
    for (int kk = 0; kk < 8; kk++) {
        int k0 = kk * 16;
        uint32_t a0, a1, a2, a3;
        {
            int rl = rw + ((m & 1) << 3) + l7;
            int c8 = (k0 >> 3) + (m >> 1);
            uint32_t addr = (uint32_t)__cvta_generic_to_shared(&Ash[swz_g(rl, c8)]);
            asm volatile("ldmatrix.sync.aligned.m8n8.x4.shared.b16 {%0,%1,%2,%3}, [%4];"
                         : "=r"(a0), "=r"(a1), "=r"(a2), "=r"(a3) : "r"(addr));
        }
        #pragma unroll
        for (int nb = 0; nb < 2; nb++) {
            int n0 = cw + nb * 16;
            uint32_t b0, b1, b2, b3;
            {
                int rl = k0 + ((m & 1) << 3) + l7;
                int c8 = (n0 >> 3) + (m >> 1);
                uint32_t addr = (uint32_t)__cvta_generic_to_shared(&Wsh[swz_g(rl, c8)]);
                asm volatile("ldmatrix.sync.aligned.m8n8.x4.trans.shared.b16 {%0,%1,%2,%3}, [%4];"
                             : "=r"(b0), "=r"(b1), "=r"(b2), "=r"(b3) : "r"(addr));
            }
            float* c0 = acc[nb * 2];
            float* c1 = acc[nb * 2 + 1];
            asm volatile("mma.sync.aligned.m16n8k16.row.col.f32.f16.f16.f32 "
                         "{%0,%1,%2,%3}, {%4,%5,%6,%7}, {%8,%9}, {%0,%1,%2,%3};"
                         : "+f"(c0[0]), "+f"(c0[1]), "+f"(c0[2]), "+f"(c0[3])
                         : "r"(a0), "r"(a1), "r"(a2), "r"(a3), "r"(b0), "r"(b1));
            asm volatile("mma.sync.aligned.m16n8k16.row.col.f32.f16.f16.f32 "
                         "{%0,%1,%2,%3}, {%4,%5,%6,%7}, {%8,%9}, {%0,%1,%2,%3};"
                         : "+f"(c1[0]), "+f"(c1[1]), "+f"(c1[2]), "+f"(c1[3])
                         : "r"(a0), "r"(a1), "r"(a2), "r"(a3), "r"(b2), "r"(b3));
        }
    }

    // epilogue: scale by dis[row], store fp16
    int gid  = lane >> 2;         // 0..7
    int tid4 = lane & 3;
    int r1 = row0 + rw + gid;
    int r2 = r1 + 8;
    float d1 = (r1 < N_NODES) ? g_dis[r1] : 0.f;
    float d2 = (r2 < N_NODES) ? g_dis[r2] : 0.f;
    #pragma unroll
    for (int nt = 0; nt < 4; nt++) {
        int col = cw + nt * 8 + tid4 * 2;
        if (r1 < N_NODES)
            *(__half2*)&OUT[r1 * FDIM + col] = __floats2half2_rn(acc[nt][0] * d1, acc[nt][1] * d1);
        if (r2 < N_NODES)
            *(__half2*)&OUT[r2 * FDIM + col] = __floats2half2_rn(acc[nt][2] * d2, acc[nt][3] * d2);
    }
}

// ---------------- aggregation: H[n] = act(dis[n]*(sum g[src] + g[n]) + b) ----------------
// warp per node; fp16 pairwise-tree accumulation (<=3 fp16 roundings per value),
// int4 index loads, 8-deep gather MLP.
#define H2(u) (*(__half2*)&(u))

__device__ __forceinline__ float4 cvt_h4(uint2 raw) {
    float2 a = __half22float2(H2(raw.x));
    float2 b = __half22float2(H2(raw.y));
    return make_float4(a.x, a.y, b.x, b.y);
}

__global__ __launch_bounds__(256) void k_agg(const __half* __restrict__ Gm,
                                             const float* __restrict__ bias,
                                             __half* __restrict__ H16,
                                             float* __restrict__ Hf,
                                             int relu) {
    int warp = (blockIdx.x * blockDim.x + threadIdx.x) >> 5;
    int lane = threadIdx.x & 31;
    if (warp >= N_NODES) return;
    int n = warp;
    int deg = g_deg[n];
    if (deg > MAXD) deg = MAXD;
    const uint2* G2 = (const uint2*)Gm;           // row = 32 x uint2
    const int* bk = g_bucket + n * MAXD;

    float4 s4 = cvt_h4(G2[n * 32 + lane]);        // self contribution (fp32)
    float ax = s4.x, ay = s4.y, az = s4.z, aw = s4.w;

    int i = 0;
    for (; i + 8 <= deg; i += 8) {
        int4 b0 = *(const int4*)(bk + i);
        int4 b1 = *(const int4*)(bk + i + 4);
        uint2 v0 = G2[b0.x * 32 + lane];
        uint2 v1 = G2[b0.y * 32 + lane];
        uint2 v2 = G2[b0.z * 32 + lane];
        uint2 v3 = G2[b0.w * 32 + lane];
        uint2 v4 = G2[b1.x * 32 + lane];
        uint2 v5 = G2[b1.y * 32 + lane];
        uint2 v6 = G2[b1.z * 32 + lane];
        uint2 v7 = G2[b1.w * 32 + lane];
        // fp16 tree (depth 3) on both half2 components
        __half2 sx = __hadd2(__hadd2(__hadd2(H2(v0.x), H2(v1.x)),
                                     __hadd2(H2(v2.x), H2(v3.x))),
                             __hadd2(__hadd2(H2(v4.x), H2(v5.x)),
                                     __hadd2(H2(v6.x), H2(v7.x))));
        __half2 sy = __hadd2(__hadd2(__hadd2(H2(v0.y), H2(v1.y)),
                                     __hadd2(H2(v2.y), H2(v3.y))),
                             __hadd2(__hadd2(H2(v4.y), H2(v5.y)),
                                     __hadd2(H2(v6.y), H2(v7.y))));
        float2 fx = __half22float2(sx);
        float2 fy = __half22float2(sy);
        ax += fx.x; ay += fx.y; az += fy.x; aw += fy.y;
    }
    for (; i + 4 <= deg; i += 4) {
        int4 b0 = *(const int4*)(bk + i);
        uint2 v0 = G2[b0.x * 32 + lane];
        uint2 v1 = G2[b0.y * 32 + lane];
        uint2 v2 = G2[b0.z * 32 + lane];
        uint2 v3 = G2[b0.w * 32 + lane];
        __half2 sx = __hadd2(__hadd2(H2(v0.x), H2(v1.x)),
                             __hadd2(H2(v2.x), H2(v3.x)));
        __half2 sy = __hadd2(__hadd2(H2(v0.y), H2(v1.y)),
                             __hadd2(H2(v2.y), H2(v3.y)));
        float2 fx = __half22float2(sx);
        float2 fy = __half22float2(sy);
        ax += fx.x; ay += fx.y; az += fy.x; aw += fy.y;
    }
    for (; i < deg; i++) {
        float4 v = cvt_h4(G2[bk[i] * 32 + lane]);
        ax += v.x; ay += v.y; az += v.z; aw += v.w;
    }

    float d = g_dis[n];
    float4 bb = ((const float4*)bias)[lane];
    float ox = d * ax + bb.x;
    float oy = d * ay + bb.y;
    float oz = d * az + bb.z;
    float ow = d * aw + bb.w;
    if (relu) {
        ox = fmaxf(ox, 0.f); oy = fmaxf(oy, 0.f);
        oz = fmaxf(oz, 0.f); ow = fmaxf(ow, 0.f);
        uint2 o;
        *(__half2*)&o.x = __floats2half2_rn(ox, oy);
        *(__half2*)&o.y = __floats2half2_rn(oz, ow);
        ((uint2*)H16)[n * 32 + lane] = o;
    } else {
        ((float4*)Hf)[n * 32 + lane] = make_float4(ox, oy, oz, ow);
    }
}

// ---------------- mean pool: one block per graph, 4 warps split rows ----------------
__global__ __launch_bounds__(128) void k_pool(const float* __restrict__ H,
                                              float* __restrict__ out) {
    __shared__ float red[4][FDIM];
    int g    = blockIdx.x;
    int lane = threadIdx.x & 31;
    int warp = threadIdx.x >> 5;
    int s = g_starts[g];
    int e = g_starts[g + 1];
    float4 acc = make_float4(0.f, 0.f, 0.f, 0.f);
    for (int n = s + warp; n < e; n += 4) {
        float4 v = ((const float4*)H)[n * 32 + lane];
        acc.x += v.x; acc.y += v.y; acc.z += v.z; acc.w += v.w;
    }
    *(float4*)&red[warp][lane * 4] = acc;
    __syncthreads();
    int t = threadIdx.x;   // 0..127 = feature dim
    float sum = red[0][t] + red[1][t] + red[2][t] + red[3][t];
    float cnt = (float)(e - s);
    out[g * FDIM + t] = sum / fmaxf(cnt, 1.0f);
}

// ---------------- launch ----------------
extern "C" void kernel_launch(void* const* d_in, const int* in_sizes, int n_in,
                              void* d_out, int out_size) {
    const float* x     = (const float*)d_in[0];
    const int*   ei    = (const int*)d_in[1];
    const int*   batch = (const int*)d_in[2];
    const float* W0    = (const float*)d_in[3];
    const float* b0    = (const float*)d_in[4];
    const float* W1    = (const float*)d_in[5];
    const float* b1    = (const float*)d_in[6];
    const float* W2    = (const float*)d_in[7];
    const float* b2    = (const float*)d_in[8];
    float* out = (float*)d_out;

    const int* src = ei;
    const int* dst = ei + N_EDGES;

    int*    dg;   cudaGetSymbolAddress((void**)&dg,   g_deg);
    __half* gbuf; cudaGetSymbolAddress((void**)&gbuf, g_gbuf);
    __half* h16;  cudaGetSymbolAddress((void**)&h16,  g_h16);
    float*  hbuf; cudaGetSymbolAddress((void**)&hbuf, g_hbuf);

    // CSR build + dis + graph starts
    cudaMemsetAsync(dg, 0, N_NODES * sizeof(int));
    k_bucket8<<<(N_EDGES / 8 + 255) / 256, 256>>>(src, dst);
    k_dis_starts<<<(N_NODES + 255) / 256, 256>>>(batch);

    const int gemm_grid = (N_NODES + 63) / 64;           // 157
    const int agg_grid  = (N_NODES * 32 + 255) / 256;

    // layer 0 (fp32 X input, fused conversion)
    k_gemm<true><<<gemm_grid, 512>>>((const void*)x, W0, gbuf);
    k_agg<<<agg_grid, 256>>>(gbuf, b0, h16, hbuf, 1);
    // layer 1
    k_gemm<false><<<gemm_grid, 512>>>((const void*)h16, W1, gbuf);
    k_agg<<<agg_grid, 256>>>(gbuf, b1, h16, hbuf, 1);
    // layer 2
    k_gemm<false><<<gemm_grid, 512>>>((const void*)h16, W2, gbuf);
    k_agg<<<agg_grid, 256>>>(gbuf, b2, h16, hbuf, 0);

    // mean pool
    k_pool<<<NGRAPH, FDIM>>>(hbuf, out);
}